// round 9
// baseline (speedup 1.0000x reference)
#include <cuda_runtime.h>
#include <cstdint>
#include <cstddef>

// Adaptive separable convolution (SepConv), sm_103a.
// out[b,c,y,w] = sum_i sum_j inp[b,c,y+i,w+j] * V[b,i,y,w] * Hz[b,j,y,w]
//
// Round-9: double-buffered shared-memory pipeline.
//  * FFMA2 (fma.rn.f32x2) packed math, 4 adjacent output pixels per thread,
//    one channel per CTA, TILE 128x4, 128-thread CTAs, 3 CTAs/SM.
//  * i-loop runs in steps of 2 with ping-pong q registers: row i+1 is loaded
//    while row i is consumed -> the ~29cyc LDS latency (the stall that pinned
//    issue at ~29% in R3-R8) is covered by a full FFMA2 block.
//  * 4 compile-time phases of 8/6/6/8 tap-pairs (bases m = 0,8,14,20 -> byte
//    offsets 0,64,112,160, all 16B-aligned -> dense conflict-free LDS.128).
//    Small phases keep live regs ~140 (w 64 + qA/qB 32 + acc) -> no spills.
//  * rolling V prefetch folded into the same 2-step structure.

#define KF   51
#define BB   2
#define CC   3
#define HH   256
#define WW   256
#define HW   (HH * WW)            // 65536
#define IN_H (HH + KF - 1)        // 306
#define IN_W (WW + KF - 1)        // 306

#define TILE_W 128
#define TILE_H 4
#define PATCH_H (TILE_H + KF - 1) // 54
#define PATCH_W (TILE_W + KF - 1) // 178
#define PATCH_WP 180              // padded row: 720B; cols 178,179 zeroed
#define ROW_BYTES (PATCH_WP * 4)  // 720

#define NTHREADS 128              // 4 warps, one output row each

__device__ __forceinline__ uint64_t pk2(float lo, float hi) {
    uint64_t r;
    asm("mov.b64 %0, {%1,%2};" : "=l"(r) : "f"(lo), "f"(hi));
    return r;
}
__device__ __forceinline__ void ffma2(uint64_t& acc, uint64_t a, uint64_t b) {
    asm("fma.rn.f32x2 %0, %1, %2, %0;" : "+l"(acc) : "l"(a), "l"(b));
}
__device__ __forceinline__ float hadd2(uint64_t p) {
    float lo, hi;
    asm("mov.b64 {%0,%1}, %2;" : "=f"(lo), "=f"(hi) : "l"(p));
    return lo + hi;
}
__device__ __forceinline__ void lds128(uint64_t& q0, uint64_t& q1, uint32_t saddr) {
    asm("ld.shared.v2.u64 {%0,%1}, [%2];" : "=l"(q0), "=l"(q1) : "r"(saddr));
}

// One phase: tap-pairs m = MBASE .. MBASE+NP-1 (NP even, 8*MBASE % 16 == 0).
template<int MBASE, int NP>
__device__ __forceinline__ void run_phase(
    const float* __restrict__ Hb, const float* __restrict__ Vb,
    uint32_t smbase, float& r0, float& r1, float& r2, float& r3)
{
    // packed weights: w[p][r] = (Hz[2m-p], Hz[2m+1-p]), m = MBASE + r.
    uint64_t w[4][NP];
#pragma unroll
    for (int p = 0; p < 4; ++p) {
#pragma unroll
        for (int r = 0; r < NP; ++r) {
            int m  = MBASE + r;
            int j0 = 2 * m - p;
            int j1 = j0 + 1;
            float f0 = (j0 >= 0 && j0 < KF) ? Hb[(size_t)j0 * HW + p] : 0.0f;
            float f1 = (j1 >= 0 && j1 < KF) ? Hb[(size_t)j1 * HW + p] : 0.0f;
            w[p][r] = pk2(f0, f1);
        }
    }

    const uint32_t sbase = smbase + (uint32_t)(8 * MBASE);
    uint64_t qA[NP], qB[NP];
    uint64_t o0 = 0, o1 = 0, o2 = 0, o3 = 0;

    auto ldq = [&](uint64_t (&q)[NP], int row) {
        uint32_t a = sbase + (uint32_t)row * ROW_BYTES;
#pragma unroll
        for (int t = 0; t < NP / 2; ++t)
            lds128(q[2 * t], q[2 * t + 1], a + 16u * t);
    };
    auto comp = [&](const uint64_t (&q)[NP], float4 v) {
        uint64_t a0 = 0, a1 = 0, a2 = 0, a3 = 0;
#pragma unroll
        for (int r = 0; r < NP; ++r) {
            ffma2(a0, w[0][r], q[r]);
            ffma2(a1, w[1][r], q[r]);
            ffma2(a2, w[2][r], q[r]);
            ffma2(a3, w[3][r], q[r]);
        }
        ffma2(o0, pk2(v.x, v.x), a0);
        ffma2(o1, pk2(v.y, v.y), a1);
        ffma2(o2, pk2(v.z, v.z), a2);
        ffma2(o3, pk2(v.w, v.w), a3);
    };

    // software pipeline: load row i+1 / i+2 before consuming row i / i+1
    ldq(qA, 0);
    float4 v4 = *(const float4*)Vb;
#pragma unroll 1
    for (int i = 0; i < KF - 1; i += 2) {      // i = 0,2,...,48
        ldq(qB, i + 1);
        float4 vn = *(const float4*)(Vb + (size_t)(i + 1) * HW);
        comp(qA, v4);                          // row i
        ldq(qA, i + 2);                        // row i+2 <= 50 (in-bounds)
        float4 vnn = *(const float4*)(Vb + (size_t)(i + 2) * HW);
        comp(qB, vn);                          // row i+1
        v4 = vnn;
    }
    comp(qA, v4);                              // row 50 (epilogue)

    r0 += hadd2(o0);
    r1 += hadd2(o1);
    r2 += hadd2(o2);
    r3 += hadd2(o3);
}

__global__ void __launch_bounds__(NTHREADS, 3)
sepconv_kernel(const float* __restrict__ inp,
               const float* __restrict__ ver,
               const float* __restrict__ hor,
               float* __restrict__ out)
{
    __shared__ __align__(16) float sm[PATCH_H][PATCH_WP];

    const int bx = blockIdx.x;            // 0..1   tile col
    const int by = blockIdx.y;            // 0..63  tile row
    const int bc = blockIdx.z;            // 0..5   (b, c) fused
    const int b  = bc / CC;
    const int c  = bc - b * CC;
    const int x0 = bx * TILE_W;
    const int y0 = by * TILE_H;

    const int tid  = threadIdx.x;
    const int lane = tid & 31;
    const int wy   = tid >> 5;            // warp id == row within tile
    const int y    = y0 + wy;             // output row
    const int w0   = x0 + 4 * lane;       // first of 4 output cols

    const float* Hb = hor + ((size_t)b * KF * HW) + (size_t)y * WW + w0;
    const float* Vb = ver + ((size_t)b * KF * HW) + (size_t)y * WW + w0;

    // ---- single patch fill for this CTA's channel (+ zero pad cols) ----
    {
        const float* src = inp + ((size_t)(b * CC + c) * IN_H + y0) * IN_W + x0;
        for (int t = tid; t < PATCH_H * (PATCH_W / 2); t += NTHREADS) {
            int r  = t / (PATCH_W / 2);
            int c2 = t - r * (PATCH_W / 2);
            float2 v = *(const float2*)(src + (size_t)r * IN_W + 2 * c2);
            *(float2*)(&sm[r][2 * c2]) = v;
        }
        if (tid < PATCH_H) {              // pad cols read by the dead pair m=27
            sm[tid][PATCH_W]     = 0.0f;
            sm[tid][PATCH_W + 1] = 0.0f;
        }
    }
    __syncthreads();

    // per-thread shared base address: row wy (+i), float col 4*lane
    const uint32_t smbase = (uint32_t)__cvta_generic_to_shared(&sm[0][0])
                          + (uint32_t)(wy * ROW_BYTES) + (uint32_t)(lane * 16);

    float res0 = 0.0f, res1 = 0.0f, res2 = 0.0f, res3 = 0.0f;

    // phases: m = 0..7, 8..13, 14..19, 20..27  (byte bases 0,64,112,160)
    run_phase<0,  8>(Hb, Vb, smbase, res0, res1, res2, res3);
    __syncthreads();
    run_phase<8,  6>(Hb, Vb, smbase, res0, res1, res2, res3);
    __syncthreads();
    run_phase<14, 6>(Hb, Vb, smbase, res0, res1, res2, res3);
    __syncthreads();
    run_phase<20, 8>(Hb, Vb, smbase, res0, res1, res2, res3);

    // ---- write out ----
    float* o = out + ((size_t)(b * CC + c) * HH + y) * WW + w0;
    *(float4*)o = make_float4(res0, res1, res2, res3);
}

extern "C" void kernel_launch(void* const* d_in, const int* in_sizes, int n_in,
                              void* d_out, int out_size)
{
    (void)in_sizes; (void)n_in; (void)out_size;
    const float* inp = (const float*)d_in[0];   // [B, C, 306, 306]
    const float* ver = (const float*)d_in[1];   // [B, 51, 256, 256]
    const float* hor = (const float*)d_in[2];   // [B, 51, 256, 256]
    float*       out = (float*)d_out;           // [B, C, 256, 256]

    dim3 grid(WW / TILE_W, HH / TILE_H, BB * CC);   // (2, 64, 6) = 768 blocks
    dim3 block(NTHREADS);
    sepconv_kernel<<<grid, block>>>(inp, ver, hor, out);
}

// round 10
// speedup vs baseline: 1.0562x; 1.0562x over previous
#include <cuda_runtime.h>
#include <cstdint>
#include <cstddef>

// Adaptive separable convolution (SepConv), sm_103a.
// out[b,c,y,w] = sum_i sum_j inp[b,c,y+i,w+j] * V[b,i,y,w] * Hz[b,j,y,w]
//
// Round-10 = R8's lean 2-buffer-free stream + R9's validated ping-pong LDS
// pipeline, at the register-feasible phase count:
//  * FFMA2 (fma.rn.f32x2) packed math, 4 adjacent output pixels per thread,
//    one channel per CTA, TILE 128x4, 128-thread CTAs, 3 CTAs/SM.
//  * 3 compile-time phases of 10/10/8 tap-pairs (byte bases 0/80/160, all
//    16B-aligned -> dense conflict-free LDS.128). w(80)+q(40) regs -> ~155.
//  * i-loop in steps of 2 with ping-pong qA/qB: row i+1 loads issue before
//    row i's FFMA2 block -> LDS latency covered (R9: issue/fma rates up).
//  * rolling V prefetch in the same 2-step structure.

#define KF   51
#define BB   2
#define CC   3
#define HH   256
#define WW   256
#define HW   (HH * WW)            // 65536
#define IN_H (HH + KF - 1)        // 306
#define IN_W (WW + KF - 1)        // 306

#define TILE_W 128
#define TILE_H 4
#define PATCH_H (TILE_H + KF - 1) // 54
#define PATCH_W (TILE_W + KF - 1) // 178
#define PATCH_WP 180              // padded row: 720B; cols 178,179 zeroed
#define ROW_BYTES (PATCH_WP * 4)  // 720

#define NTHREADS 128              // 4 warps, one output row each

__device__ __forceinline__ uint64_t pk2(float lo, float hi) {
    uint64_t r;
    asm("mov.b64 %0, {%1,%2};" : "=l"(r) : "f"(lo), "f"(hi));
    return r;
}
__device__ __forceinline__ void ffma2(uint64_t& acc, uint64_t a, uint64_t b) {
    asm("fma.rn.f32x2 %0, %1, %2, %0;" : "+l"(acc) : "l"(a), "l"(b));
}
__device__ __forceinline__ float hadd2(uint64_t p) {
    float lo, hi;
    asm("mov.b64 {%0,%1}, %2;" : "=f"(lo), "=f"(hi) : "l"(p));
    return lo + hi;
}
__device__ __forceinline__ void lds128(uint64_t& q0, uint64_t& q1, uint32_t saddr) {
    asm("ld.shared.v2.u64 {%0,%1}, [%2];" : "=l"(q0), "=l"(q1) : "r"(saddr));
}

// One phase: tap-pairs m = MBASE .. MBASE+NP-1 (NP even, 8*MBASE % 16 == 0).
template<int MBASE, int NP>
__device__ __forceinline__ void run_phase(
    const float* __restrict__ Hb, const float* __restrict__ Vb,
    uint32_t smbase, float& r0, float& r1, float& r2, float& r3)
{
    // packed weights: w[p][r] = (Hz[2m-p], Hz[2m+1-p]), m = MBASE + r.
    uint64_t w[4][NP];
#pragma unroll
    for (int p = 0; p < 4; ++p) {
#pragma unroll
        for (int r = 0; r < NP; ++r) {
            int m  = MBASE + r;
            int j0 = 2 * m - p;
            int j1 = j0 + 1;
            float f0 = (j0 >= 0 && j0 < KF) ? Hb[(size_t)j0 * HW + p] : 0.0f;
            float f1 = (j1 >= 0 && j1 < KF) ? Hb[(size_t)j1 * HW + p] : 0.0f;
            w[p][r] = pk2(f0, f1);
        }
    }

    const uint32_t sbase = smbase + (uint32_t)(8 * MBASE);
    uint64_t qA[NP], qB[NP];
    uint64_t o0 = 0, o1 = 0, o2 = 0, o3 = 0;

    auto ldq = [&](uint64_t (&q)[NP], int row) {
        uint32_t a = sbase + (uint32_t)row * ROW_BYTES;
#pragma unroll
        for (int t = 0; t < NP / 2; ++t)
            lds128(q[2 * t], q[2 * t + 1], a + 16u * t);
    };
    auto comp = [&](const uint64_t (&q)[NP], float4 v) {
        uint64_t a0 = 0, a1 = 0, a2 = 0, a3 = 0;
#pragma unroll
        for (int r = 0; r < NP; ++r) {
            ffma2(a0, w[0][r], q[r]);
            ffma2(a1, w[1][r], q[r]);
            ffma2(a2, w[2][r], q[r]);
            ffma2(a3, w[3][r], q[r]);
        }
        ffma2(o0, pk2(v.x, v.x), a0);
        ffma2(o1, pk2(v.y, v.y), a1);
        ffma2(o2, pk2(v.z, v.z), a2);
        ffma2(o3, pk2(v.w, v.w), a3);
    };

    // software pipeline: load row i+1 / i+2 before consuming row i / i+1
    ldq(qA, 0);
    float4 v4 = *(const float4*)Vb;
#pragma unroll 1
    for (int i = 0; i < KF - 1; i += 2) {      // i = 0,2,...,48
        ldq(qB, i + 1);
        float4 vn = *(const float4*)(Vb + (size_t)(i + 1) * HW);
        comp(qA, v4);                          // row i
        ldq(qA, i + 2);                        // row i+2 <= 50 (in-bounds)
        float4 vnn = *(const float4*)(Vb + (size_t)(i + 2) * HW);
        comp(qB, vn);                          // row i+1
        v4 = vnn;
    }
    comp(qA, v4);                              // row 50 (epilogue)

    r0 += hadd2(o0);
    r1 += hadd2(o1);
    r2 += hadd2(o2);
    r3 += hadd2(o3);
}

__global__ void __launch_bounds__(NTHREADS, 3)
sepconv_kernel(const float* __restrict__ inp,
               const float* __restrict__ ver,
               const float* __restrict__ hor,
               float* __restrict__ out)
{
    __shared__ __align__(16) float sm[PATCH_H][PATCH_WP];

    const int bx = blockIdx.x;            // 0..1   tile col
    const int by = blockIdx.y;            // 0..63  tile row
    const int bc = blockIdx.z;            // 0..5   (b, c) fused
    const int b  = bc / CC;
    const int c  = bc - b * CC;
    const int x0 = bx * TILE_W;
    const int y0 = by * TILE_H;

    const int tid  = threadIdx.x;
    const int lane = tid & 31;
    const int wy   = tid >> 5;            // warp id == row within tile
    const int y    = y0 + wy;             // output row
    const int w0   = x0 + 4 * lane;       // first of 4 output cols

    const float* Hb = hor + ((size_t)b * KF * HW) + (size_t)y * WW + w0;
    const float* Vb = ver + ((size_t)b * KF * HW) + (size_t)y * WW + w0;

    // ---- single patch fill for this CTA's channel (+ zero pad cols) ----
    {
        const float* src = inp + ((size_t)(b * CC + c) * IN_H + y0) * IN_W + x0;
        for (int t = tid; t < PATCH_H * (PATCH_W / 2); t += NTHREADS) {
            int r  = t / (PATCH_W / 2);
            int c2 = t - r * (PATCH_W / 2);
            float2 v = *(const float2*)(src + (size_t)r * IN_W + 2 * c2);
            *(float2*)(&sm[r][2 * c2]) = v;
        }
        if (tid < PATCH_H) {              // pad cols read by the dead pair m=27
            sm[tid][PATCH_W]     = 0.0f;
            sm[tid][PATCH_W + 1] = 0.0f;
        }
    }
    __syncthreads();

    // per-thread shared base address: row wy (+i), float col 4*lane
    const uint32_t smbase = (uint32_t)__cvta_generic_to_shared(&sm[0][0])
                          + (uint32_t)(wy * ROW_BYTES) + (uint32_t)(lane * 16);

    float res0 = 0.0f, res1 = 0.0f, res2 = 0.0f, res3 = 0.0f;

    // phases: m = 0..9, 10..19, 20..27  (byte bases 0, 80, 160; all 16B-aligned)
    run_phase<0,  10>(Hb, Vb, smbase, res0, res1, res2, res3);
    __syncthreads();   // liveness fence: keep next phase's weight loads below
    run_phase<10, 10>(Hb, Vb, smbase, res0, res1, res2, res3);
    __syncthreads();
    run_phase<20, 8>(Hb, Vb, smbase, res0, res1, res2, res3);

    // ---- write out ----
    float* o = out + ((size_t)(b * CC + c) * HH + y) * WW + w0;
    *(float4*)o = make_float4(res0, res1, res2, res3);
}

extern "C" void kernel_launch(void* const* d_in, const int* in_sizes, int n_in,
                              void* d_out, int out_size)
{
    (void)in_sizes; (void)n_in; (void)out_size;
    const float* inp = (const float*)d_in[0];   // [B, C, 306, 306]
    const float* ver = (const float*)d_in[1];   // [B, 51, 256, 256]
    const float* hor = (const float*)d_in[2];   // [B, 51, 256, 256]
    float*       out = (float*)d_out;           // [B, C, 256, 256]

    dim3 grid(WW / TILE_W, HH / TILE_H, BB * CC);   // (2, 64, 6) = 768 blocks
    dim3 block(NTHREADS);
    sepconv_kernel<<<grid, block>>>(inp, ver, hor, out);
}